// round 2
// baseline (speedup 1.0000x reference)
#include <cuda_runtime.h>
#include <cstdint>

#define NB      8192
#define MDIM    32
#define NDIM    16
#define MAXIT   100
#define TOLF    1e-2f
#define ALPHAF  0.5f

typedef unsigned long long u64;

// ---- static device scratch (no dynamic allocation anywhere) ----
__device__ float  g_K    [NB * NDIM * NDIM];                 // 8 MB
__device__ float  g_T1   [NB * NDIM * NDIM];                 // 8 MB
__device__ float2 g_zhist[(size_t)NB * MAXIT * 32];          // ~210 MB
__device__ int    g_flags[MAXIT + 1];
__device__ int    g_J;

// ---- packed fp32x2 helpers (FFMA2 path, sm_100+) ----
__device__ __forceinline__ u64 fma2(u64 a, u64 b, u64 c) {
    u64 d; asm("fma.rn.f32x2 %0,%1,%2,%3;" : "=l"(d) : "l"(a), "l"(b), "l"(c)); return d;
}
__device__ __forceinline__ u64 add2(u64 a, u64 b) {
    u64 d; asm("add.rn.f32x2 %0,%1,%2;" : "=l"(d) : "l"(a), "l"(b)); return d;
}
__device__ __forceinline__ float red2(u64 a) {
    float lo, hi; asm("mov.b64 {%0,%1},%2;" : "=f"(lo), "=f"(hi) : "l"(a)); return lo + hi;
}
__device__ __forceinline__ u64 pk2(float lo, float hi) {
    u64 d; asm("mov.b64 %0,{%1,%2};" : "=l"(d) : "f"(lo), "f"(hi)); return d;
}

// 16-element dot: a[0..7] (packed pairs) . v[0..7] (packed pairs)
__device__ __forceinline__ float dot16p(const u64* a, const u64* v) {
    u64 c0 = fma2(a[0], v[0], 0ull);
    u64 c1 = fma2(a[1], v[1], 0ull);
    u64 c2 = fma2(a[2], v[2], 0ull);
    u64 c3 = fma2(a[3], v[3], 0ull);
    c0 = fma2(a[4], v[4], c0);
    c1 = fma2(a[5], v[5], c1);
    c2 = fma2(a[6], v[6], c2);
    c3 = fma2(a[7], v[7], c3);
    return red2(add2(add2(c0, c1), add2(c2, c3)));
}

// -------------------------------------------------------------------------
__global__ void init_flags_kernel() {
    int t = threadIdx.x;
    if (t <= MAXIT) g_flags[t] = 0;
}

// -------------------------------------------------------------------------
// Per-batch precompute: K = (0.5 I + A^T A)^{-1}  (16x16),  T1 = I - (A^T A) K.
__global__ void __launch_bounds__(128) precompute_kernel(const float* __restrict__ A_g) {
    __shared__ __align__(16) float A_sh [4][MDIM * NDIM];
    __shared__ __align__(16) float F_sh [4][NDIM * NDIM];
    __shared__ float aug_sh[4][NDIM * 33];
    __shared__ float f_sh  [4][NDIM];

    const int lane  = threadIdx.x & 31;
    const int w     = threadIdx.x >> 5;
    const int batch = blockIdx.x * 4 + w;

    const float4* Ab4 = reinterpret_cast<const float4*>(A_g + (size_t)batch * MDIM * NDIM);
    float4* As4 = reinterpret_cast<float4*>(A_sh[w]);
#pragma unroll
    for (int j = 0; j < 4; j++) As4[lane * 4 + j] = Ab4[lane * 4 + j];
    __syncwarp();

    if (lane < NDIM) {
        float acc[16];
#pragma unroll
        for (int j = 0; j < 16; j++) acc[j] = 0.f;
#pragma unroll 4
        for (int k = 0; k < MDIM; k++) {
            float aki = A_sh[w][k * NDIM + lane];
            const float4* row = reinterpret_cast<const float4*>(&A_sh[w][k * NDIM]);
            float4 r0 = row[0], r1 = row[1], r2 = row[2], r3 = row[3];
            acc[0]  += aki * r0.x;  acc[1]  += aki * r0.y;
            acc[2]  += aki * r0.z;  acc[3]  += aki * r0.w;
            acc[4]  += aki * r1.x;  acc[5]  += aki * r1.y;
            acc[6]  += aki * r1.z;  acc[7]  += aki * r1.w;
            acc[8]  += aki * r2.x;  acc[9]  += aki * r2.y;
            acc[10] += aki * r2.z;  acc[11] += aki * r2.w;
            acc[12] += aki * r3.x;  acc[13] += aki * r3.y;
            acc[14] += aki * r3.z;  acc[15] += aki * r3.w;
        }
#pragma unroll
        for (int j = 0; j < 16; j++) F_sh[w][lane * 16 + j] = acc[j];
    }
    __syncwarp();

#pragma unroll
    for (int r = 0; r < NDIM; r++) {
        float v;
        if (lane < 16) v = F_sh[w][r * 16 + lane] + ((r == lane) ? 0.5f : 0.f);
        else           v = ((lane - 16) == r) ? 1.f : 0.f;
        aug_sh[w][r * 33 + lane] = v;
    }
    __syncwarp();

#pragma unroll 1
    for (int p = 0; p < NDIM; p++) {
        float piv = 1.0f / aug_sh[w][p * 33 + p];
        if (lane < NDIM) f_sh[w][lane] = aug_sh[w][lane * 33 + p];
        __syncwarp();
        float prow = aug_sh[w][p * 33 + lane] * piv;
        aug_sh[w][p * 33 + lane] = prow;
#pragma unroll
        for (int r = 0; r < NDIM; r++) {
            if (r != p) aug_sh[w][r * 33 + lane] -= f_sh[w][r] * prow;
        }
        __syncwarp();
    }

#pragma unroll
    for (int e = 0; e < 8; e++) {
        int idx = e * 32 + lane;
        int i = idx >> 4, j = idx & 15;
        float kv = aug_sh[w][i * 33 + 16 + j];
        g_K[(size_t)batch * 256 + idx] = kv;
        float s = (i == j) ? 1.f : 0.f;
#pragma unroll
        for (int m = 0; m < 16; m++)
            s -= F_sh[w][i * 16 + m] * aug_sh[w][m * 33 + 16 + j];
        g_T1[(size_t)batch * 256 + idx] = s;
    }
}

// -------------------------------------------------------------------------
// One warp per batch. Runs all 100 T-steps, records z_k history + per-k
// "any residual >= TOL" flags. All dot products use packed f32x2 FMA.
__global__ void __launch_bounds__(128) iterate_kernel(
        const float* __restrict__ u_g,
        const float* __restrict__ A_g,
        const float* __restrict__ b_g) {
    __shared__ __align__(16) float q_sh [4][16];
    __shared__ __align__(16) float r_sh [4][32];
    __shared__ __align__(16) float h_sh [4][16];
    __shared__ __align__(16) float g2_sh[4][16];
    __shared__ __align__(16) float t_sh [4][16];

    const int lane  = threadIdx.x & 31;
    const int w     = threadIdx.x >> 5;
    const int batch = blockIdx.x * 4 + w;
    const int i16   = lane & 15;
    const int half  = lane >> 4;               // 0 or 1
    const float sgn = half ? -1.f : 1.f;
    const int kbase = half * 16;

    const float* Ab = A_g + (size_t)batch * 512;

    // A row `lane` as 8 packed f32x2
    u64 ar[8];
    {
        const ulonglong2* Ab2 = reinterpret_cast<const ulonglong2*>(Ab);
#pragma unroll
        for (int j = 0; j < 4; j++) {
            ulonglong2 v = Ab2[lane * 4 + j];
            ar[2 * j] = v.x; ar[2 * j + 1] = v.y;
        }
    }

    // A^T half column, packed over consecutive k: at2[t] = (A[kb+2t][i16], A[kb+2t+1][i16])
    u64 at2[8];
#pragma unroll
    for (int t = 0; t < 8; t++)
        at2[t] = pk2(Ab[(kbase + 2 * t) * 16 + i16], Ab[(kbase + 2 * t + 1) * 16 + i16]);

    // M row: K row i16 (lanes<16) or T1 row i16 (lanes>=16), packed
    u64 mr2[8];
    {
        const ulonglong2* Mb2 = reinterpret_cast<const ulonglong2*>(
            (half ? g_T1 : g_K) + (size_t)batch * 256 + i16 * 16);
#pragma unroll
        for (int j = 0; j < 4; j++) {
            ulonglong2 v = Mb2[j];
            mr2[2 * j] = v.x; mr2[2 * j + 1] = v.y;
        }
    }

    const float u_lo = u_g[batch * 16 + i16];
    const float bl   = b_g[batch * 32 + lane];

    float2* hist = g_zhist + (size_t)batch * 32 + lane;

    float z_a = 0.f, z_b = 0.f;

#pragma unroll 1
    for (int k = 1; k <= MAXIT; k++) {
        float x_a = fmaxf(z_a, 0.f);
        float x_b = fmaxf(z_b, 0.f);
        float xa_o = __shfl_xor_sync(0xffffffffu, x_a, 16);
        float za_o = __shfl_xor_sync(0xffffffffu, z_a, 16);
        float pdiff = x_a - xa_o;                 // lane<16: x1-x2 ; lane>=16: -(x1-x2)

        // q = p - (z1 - z2) + u   (alpha = 0.5)
        if (lane < 16) q_sh[w][lane] = pdiff - (z_a - za_o) + u_lo;
        __syncwarp();

        // r_l = 2*x3 - z3 - b + (A q)_l
        u64 qp[8];
        {
            const ulonglong2* qv = reinterpret_cast<const ulonglong2*>(&q_sh[w][0]);
#pragma unroll
            for (int j = 0; j < 4; j++) { ulonglong2 v = qv[j]; qp[2*j] = v.x; qp[2*j+1] = v.y; }
        }
        float r = 2.f * x_b - z_b - bl + dot16p(ar, qp);
        r_sh[w][lane] = r;
        __syncwarp();

        // h = A^T r  (each half-warp sums half the k range, combine by xor-16)
        u64 rp[8];
        {
            const ulonglong2* rv = reinterpret_cast<const ulonglong2*>(&r_sh[w][kbase]);
#pragma unroll
            for (int j = 0; j < 4; j++) { ulonglong2 v = rv[j]; rp[2*j] = v.x; rp[2*j+1] = v.y; }
        }
        float hp = dot16p(at2, rp);
        hp += __shfl_xor_sync(0xffffffffu, hp, 16);
        if (lane < 16) h_sh[w][lane] = hp;
        __syncwarp();

        // lanes<16: g2 = K h ; lanes>=16: t = T1 h
        u64 hpk[8];
        {
            const ulonglong2* hv = reinterpret_cast<const ulonglong2*>(&h_sh[w][0]);
#pragma unroll
            for (int j = 0; j < 4; j++) { ulonglong2 v = hv[j]; hpk[2*j] = v.x; hpk[2*j+1] = v.y; }
        }
        float val = dot16p(mr2, hpk);
        if (lane < 16) g2_sh[w][lane] = val;
        else           t_sh[w][i16]  = val;
        __syncwarp();

        // w_l = r_l - (A g2)_l
        u64 gp[8];
        {
            const ulonglong2* gv = reinterpret_cast<const ulonglong2*>(&g2_sh[w][0]);
#pragma unroll
            for (int j = 0; j < 4; j++) { ulonglong2 v = gv[j]; gp[2*j] = v.x; gp[2*j+1] = v.y; }
        }
        float wv = r - dot16p(ar, gp);
        float tval = t_sh[w][i16];

        // z1' = x1 - a*d - t ; z2' = x2 + a*d + t ; z3' = x3 - w
        float grad_a = pdiff - sgn * u_lo;        // = sgn * d
        float zan = x_a - ALPHAF * grad_a - sgn * tval;
        float zbn = x_b - wv;

        float res = fmaxf(fabsf(zan - z_a), fabsf(zbn - z_b));
        unsigned above = __any_sync(0xffffffffu, res >= TOLF);
        if (above && lane == 0 && k < MAXIT) g_flags[k] = 1;

        hist[(size_t)(k - 1) * NB * 32] = make_float2(zan, zbn);

        z_a = zan; z_b = zbn;
    }
}

// -------------------------------------------------------------------------
// J = number of while-loop steps: first k in [1,99] with all residuals < TOL,
// else 99. Parallel min-reduction.
__global__ void select_kernel() {
    __shared__ int s;
    int t = threadIdx.x;
    if (t == 0) s = MAXIT - 1;
    __syncthreads();
    int k = t + 1;                       // 1..128
    if (k <= MAXIT - 1 && g_flags[k] == 0) atomicMin(&s, k);
    __syncthreads();
    if (t == 0) g_J = s;
}

// z_star = z_{J+1} (history slot J). out = [u_star (8192x16), z_star (8192x64)].
// hist layout: slot J, batch b, lane l -> float2(z[l], z[32+l])
__global__ void output_kernel(float* __restrict__ out) {
    int J = g_J;
    int idx = blockIdx.x * blockDim.x + threadIdx.x;
    if (idx >= NB * 64) return;
    int b = idx >> 6;
    int j = idx & 63;
    size_t base = ((size_t)J * NB + b) * 32;
    float2 vlo = g_zhist[base + (j & 31)];
    float z = (j < 32) ? vlo.x : vlo.y;
    out[NB * 16 + idx] = z;
    if (j < 16) {
        float2 vhi = g_zhist[base + 16 + j];
        out[b * 16 + j] = vlo.x - vhi.x;   // u = z1 - z2
    }
}

// -------------------------------------------------------------------------
extern "C" void kernel_launch(void* const* d_in, const int* in_sizes, int n_in,
                              void* d_out, int out_size) {
    const float* u_nom = (const float*)d_in[0];
    const float* A     = (const float*)d_in[1];
    const float* b     = (const float*)d_in[2];
    float* out = (float*)d_out;

    init_flags_kernel<<<1, 128>>>();
    precompute_kernel<<<NB / 4, 128>>>(A);
    iterate_kernel<<<NB / 4, 128>>>(u_nom, A, b);
    select_kernel<<<1, 128>>>();
    output_kernel<<<(NB * 64 + 255) / 256, 256>>>(out);
}